// round 2
// baseline (speedup 1.0000x reference)
#include <cuda_runtime.h>

#define NVX 50000
#define NEX 10000
#define HD  256
#define PX  400000

// ---------------- scratch (static device globals; no runtime alloc) ----------------
__device__ float g_ve[(size_t)NVX * HD];   // relu(v @ W1^T + b1) * n_weight
__device__ float g_ev[(size_t)NEX * HD];   // relu(e_out @ W2^T + b2) * e_weight
__device__ int g_cnt_e[NEX];
__device__ int g_off_e[NEX + 1];
__device__ int g_cur_e[NEX];
__device__ int g_perm_e[PX];
__device__ int g_cnt_v[NVX];
__device__ int g_off_v[NVX + 1];
__device__ int g_cur_v[NVX];
__device__ int g_perm_v[PX];

// EDGE template flag selects which global CSR arrays a kernel touches, so the
// host launcher never needs device pointers to the globals (no cudaGetSymbolAddress
// anywhere -> kernel_launch is pure kernel launches, trivially graph-capturable).

// ---------------- CSR build ----------------
template <bool EDGE>
__global__ void k_zero() {
    int n = EDGE ? NEX : NVX;
    int* cnt = EDGE ? g_cnt_e : g_cnt_v;
    int i = blockIdx.x * blockDim.x + threadIdx.x;
    if (i < n) cnt[i] = 0;
}

template <bool EDGE>
__global__ void k_hist(const int* __restrict__ idx) {
    int* cnt = EDGE ? g_cnt_e : g_cnt_v;
    int i = blockIdx.x * blockDim.x + threadIdx.x;
    if (i < PX) atomicAdd(&cnt[idx[i]], 1);
}

// Single-block exclusive scan: thread t owns contiguous segment [t*items, (t+1)*items).
template <bool EDGE>
__global__ void k_scan() {
    const int n = EDGE ? NEX : NVX;
    const int items = (n + 1023) / 1024;
    const int* cnt = EDGE ? g_cnt_e : g_cnt_v;
    int* off = EDGE ? g_off_e : g_off_v;
    int* cur = EDGE ? g_cur_e : g_cur_v;

    __shared__ int wsum[32];
    int t = threadIdx.x;            // blockDim.x == 1024
    int lane = t & 31, wid = t >> 5;
    int start = t * items;
    int end = min(start + items, n);

    int sum = 0;
    for (int i = start; i < end; i++) sum += cnt[i];

    int v = sum;
#pragma unroll
    for (int s = 1; s < 32; s <<= 1) {
        int y = __shfl_up_sync(0xffffffffu, v, s);
        if (lane >= s) v += y;
    }
    if (lane == 31) wsum[wid] = v;
    __syncthreads();
    if (wid == 0) {
        int w = wsum[lane];
        int vi = w;
#pragma unroll
        for (int s = 1; s < 32; s <<= 1) {
            int y = __shfl_up_sync(0xffffffffu, vi, s);
            if (lane >= s) vi += y;
        }
        wsum[lane] = vi - w;   // exclusive warp offset
    }
    __syncthreads();

    int excl = wsum[wid] + (v - sum);   // block-exclusive prefix for this thread
    int run = excl;
    for (int i = start; i < end; i++) {
        off[i] = run;
        cur[i] = run;
        run += cnt[i];
    }
    if (t == 1023) off[n] = run;   // thread 1023's segment ends at/past n -> run == total
}

template <bool EDGE>
__global__ void k_fill(const int* __restrict__ idx) {
    int* cur = EDGE ? g_cur_e : g_cur_v;
    int* perm = EDGE ? g_perm_e : g_perm_v;
    int i = blockIdx.x * blockDim.x + threadIdx.x;
    if (i < PX) {
        int pos = atomicAdd(&cur[idx[i]], 1);
        perm[pos] = i;
    }
}

// ---------------- GEMM: C[m,n] = relu(sum_k A[m,k]*B[n,k] + bias[n]) * rowscale[m]
// A: [M,256] row-major, B: [256,256] row-major (row n is k-contiguous).
// Writes to g_ve (EDGE=true reads vertices -> edges msg) or g_ev. ----------------
template <bool VE>
__global__ void __launch_bounds__(256, 2)
k_gemm(const float* __restrict__ A, const float* __restrict__ B,
       const float* __restrict__ bias, const float* __restrict__ rowscale, int M) {
    float* C = VE ? g_ve : g_ev;
    __shared__ float As[16][128];
    __shared__ float Bs[16][128];

    const int bm = blockIdx.x * 128;
    const int bn = blockIdx.y * 128;
    const int tid = threadIdx.x;
    const int tx = tid & 15;   // 0..15  (N direction)
    const int ty = tid >> 4;   // 0..15  (M direction)

    float acc[8][8];
#pragma unroll
    for (int i = 0; i < 8; i++)
#pragma unroll
        for (int j = 0; j < 8; j++) acc[i][j] = 0.f;

    for (int k0 = 0; k0 < 256; k0 += 16) {
#pragma unroll
        for (int i = 0; i < 2; i++) {
            int f = tid * 2 + i;        // 0..511 float4 slots
            int row = f >> 2;           // 0..127
            int c4 = f & 3;             // 0..3
            int gm = bm + row;
            float4 av = (gm < M) ? *(const float4*)&A[(size_t)gm * HD + k0 + c4 * 4]
                                 : make_float4(0.f, 0.f, 0.f, 0.f);
            As[c4 * 4 + 0][row] = av.x;
            As[c4 * 4 + 1][row] = av.y;
            As[c4 * 4 + 2][row] = av.z;
            As[c4 * 4 + 3][row] = av.w;
            float4 wv = *(const float4*)&B[(size_t)(bn + row) * HD + k0 + c4 * 4];
            Bs[c4 * 4 + 0][row] = wv.x;
            Bs[c4 * 4 + 1][row] = wv.y;
            Bs[c4 * 4 + 2][row] = wv.z;
            Bs[c4 * 4 + 3][row] = wv.w;
        }
        __syncthreads();
#pragma unroll
        for (int kk = 0; kk < 16; kk++) {
            float a[8], b[8];
            *(float4*)&a[0] = *(const float4*)&As[kk][ty * 8];
            *(float4*)&a[4] = *(const float4*)&As[kk][ty * 8 + 4];
            *(float4*)&b[0] = *(const float4*)&Bs[kk][tx * 8];
            *(float4*)&b[4] = *(const float4*)&Bs[kk][tx * 8 + 4];
#pragma unroll
            for (int i = 0; i < 8; i++)
#pragma unroll
                for (int j = 0; j < 8; j++)
                    acc[i][j] = fmaf(a[i], b[j], acc[i][j]);
        }
        __syncthreads();
    }

#pragma unroll
    for (int i = 0; i < 8; i++) {
        int gm = bm + ty * 8 + i;
        if (gm < M) {
            float sc = rowscale[gm];
#pragma unroll
            for (int j = 0; j < 8; j += 4) {
                int gn = bn + tx * 8 + j;
                float4 o;
                o.x = fmaxf(acc[i][j + 0] + bias[gn + 0], 0.f) * sc;
                o.y = fmaxf(acc[i][j + 1] + bias[gn + 1], 0.f) * sc;
                o.z = fmaxf(acc[i][j + 2] + bias[gn + 2], 0.f) * sc;
                o.w = fmaxf(acc[i][j + 3] + bias[gn + 3], 0.f) * sc;
                *(float4*)&C[(size_t)gm * HD + gn] = o;
            }
        }
    }
}

// ---------------- pull-based accumulation ----------------
// e_out[j,h] = (e[j,h] + sum_{p: eidx[p]==j} g_ve[pairs_v[p],h] * n_reg_weight[p]) / e_reg_sum[j]
__global__ void k_edge_accum(const float* __restrict__ e, const int* __restrict__ pairs_v,
                             const float* __restrict__ nrw, const float* __restrict__ ers,
                             float* __restrict__ e_out) {
    __shared__ int srow[256];
    __shared__ float sw[256];
    int j = blockIdx.x;
    int h = threadIdx.x;
    int s = g_off_e[j], t = g_off_e[j + 1];
    float acc = e[(size_t)j * HD + h];
    for (int c = s; c < t; c += 256) {
        int i = c + h;
        if (i < t) {
            int p = g_perm_e[i];
            srow[h] = pairs_v[p];
            sw[h] = nrw[p];
        }
        __syncthreads();
        int m = min(256, t - c);
#pragma unroll 4
        for (int q = 0; q < m; q++)
            acc = fmaf(g_ve[(size_t)srow[q] * HD + h], sw[q], acc);
        __syncthreads();
    }
    e_out[(size_t)j * HD + h] = acc / ers[j];
}

// v_out[i,h] = (v[i,h]*n_weight[i] + sum_{p: vidx[p]==i} g_ev[pairs_e[p],h] * e_reg_weight[p]) / n_reg_sum[i]
__global__ void k_vertex_accum(const float* __restrict__ v, const int* __restrict__ pairs_e,
                               const float* __restrict__ erw, const float* __restrict__ nrs,
                               const float* __restrict__ nw, float* __restrict__ v_out) {
    __shared__ int srow[256];
    __shared__ float sw[256];
    int i0 = blockIdx.x;
    int h = threadIdx.x;
    int s = g_off_v[i0], t = g_off_v[i0 + 1];
    float acc = v[(size_t)i0 * HD + h] * nw[i0];
    for (int c = s; c < t; c += 256) {
        int i = c + h;
        if (i < t) {
            int p = g_perm_v[i];
            srow[h] = pairs_e[p];
            sw[h] = erw[p];
        }
        __syncthreads();
        int m = min(256, t - c);
#pragma unroll 4
        for (int q = 0; q < m; q++)
            acc = fmaf(g_ev[(size_t)srow[q] * HD + h], sw[q], acc);
        __syncthreads();
    }
    v_out[(size_t)i0 * HD + h] = acc / nrs[i0];
}

// ---------------- launcher: kernel launches ONLY ----------------
extern "C" void kernel_launch(void* const* d_in, const int* in_sizes, int n_in,
                              void* d_out, int out_size) {
    const float* v            = (const float*)d_in[0];
    const float* e            = (const float*)d_in[1];
    const float* W1           = (const float*)d_in[2];
    const float* b1           = (const float*)d_in[3];
    const float* W2           = (const float*)d_in[4];
    const float* b2           = (const float*)d_in[5];
    const float* n_weight     = (const float*)d_in[6];
    const float* e_weight     = (const float*)d_in[7];
    const float* n_reg_weight = (const float*)d_in[8];
    const float* e_reg_weight = (const float*)d_in[9];
    const float* e_reg_sum    = (const float*)d_in[10];
    const float* n_reg_sum    = (const float*)d_in[11];
    const int*   pairs_v      = (const int*)d_in[12];
    const int*   eidx         = (const int*)d_in[13];
    const int*   pairs_e      = (const int*)d_in[14];
    const int*   vidx         = (const int*)d_in[15];

    float* v_out = (float*)d_out;                              // [NVX, HD]
    float* e_out = (float*)d_out + (size_t)NVX * HD;           // [NEX, HD]

    // CSR for edges (by eidx)
    k_zero<true><<<(NEX + 255) / 256, 256>>>();
    k_hist<true><<<(PX + 255) / 256, 256>>>(eidx);
    k_scan<true><<<1, 1024>>>();
    k_fill<true><<<(PX + 255) / 256, 256>>>(eidx);

    // CSR for vertices (by vidx)
    k_zero<false><<<(NVX + 255) / 256, 256>>>();
    k_hist<false><<<(PX + 255) / 256, 256>>>(vidx);
    k_scan<false><<<1, 1024>>>();
    k_fill<false><<<(PX + 255) / 256, 256>>>(vidx);

    // GEMM1: g_ve = relu(v @ W1^T + b1) * n_weight
    dim3 g1((NVX + 127) / 128, 2);
    k_gemm<true><<<g1, 256>>>(v, W1, b1, n_weight, NVX);

    // edge accumulate -> e_out (written straight into d_out)
    k_edge_accum<<<NEX, 256>>>(e, pairs_v, n_reg_weight, e_reg_sum, e_out);

    // GEMM2: g_ev = relu(e_out @ W2^T + b2) * e_weight
    dim3 g2((NEX + 127) / 128, 2);
    k_gemm<false><<<g2, 256>>>(e_out, W2, b2, e_weight, NEX);

    // vertex accumulate -> v_out
    k_vertex_accum<<<NVX, 256>>>(v, pairs_e, e_reg_weight, n_reg_sum, n_weight, v_out);
}

// round 3
// speedup vs baseline: 1.3963x; 1.3963x over previous
#include <cuda_runtime.h>
#include <cuda_bf16.h>

#define NVX 50000
#define NEX 10000
#define HD  256
#define PX  400000

// ---------------- scratch (static device globals; no runtime alloc) ----------------
__device__ float g_ve[(size_t)NVX * HD];   // relu(v @ W1^T + b1) * n_weight
__device__ float g_ev[(size_t)NEX * HD];   // relu(e_out @ W2^T + b2) * e_weight
__device__ int g_cnt_e[NEX];
__device__ int g_off_e[NEX + 1];
__device__ int g_cur_e[NEX];
__device__ int g_perm_e[PX];
__device__ int g_cnt_v[NVX];
__device__ int g_off_v[NVX + 1];
__device__ int g_cur_v[NVX];
__device__ int g_perm_v[PX];

// ---------------- CSR build (fused edge+vertex) ----------------
__global__ void k_zero_all() {
    int i = blockIdx.x * blockDim.x + threadIdx.x;
    if (i < NEX) g_cnt_e[i] = 0;
    if (i < NVX) g_cnt_v[i] = 0;
}

__global__ void k_hist_all(const int* __restrict__ eidx, const int* __restrict__ vidx) {
    int i = blockIdx.x * blockDim.x + threadIdx.x;
    if (i < PX) {
        atomicAdd(&g_cnt_e[eidx[i]], 1);
        atomicAdd(&g_cnt_v[vidx[i]], 1);
    }
}

// grid=2: block 0 scans edge counters, block 1 vertex counters.
// Thread t owns contiguous segment; 2 barriers total.
__global__ void k_scan_all() {
    const bool EDGE = (blockIdx.x == 0);
    const int n = EDGE ? NEX : NVX;
    const int items = (n + 1023) / 1024;
    const int* cnt = EDGE ? g_cnt_e : g_cnt_v;
    int* off = EDGE ? g_off_e : g_off_v;
    int* cur = EDGE ? g_cur_e : g_cur_v;

    __shared__ int wsum[32];
    int t = threadIdx.x;            // blockDim.x == 1024
    int lane = t & 31, wid = t >> 5;
    int start = t * items;
    int end = min(start + items, n);

    int sum = 0;
    for (int i = start; i < end; i++) sum += cnt[i];

    int v = sum;
#pragma unroll
    for (int s = 1; s < 32; s <<= 1) {
        int y = __shfl_up_sync(0xffffffffu, v, s);
        if (lane >= s) v += y;
    }
    if (lane == 31) wsum[wid] = v;
    __syncthreads();
    if (wid == 0) {
        int w = wsum[lane];
        int vi = w;
#pragma unroll
        for (int s = 1; s < 32; s <<= 1) {
            int y = __shfl_up_sync(0xffffffffu, vi, s);
            if (lane >= s) vi += y;
        }
        wsum[lane] = vi - w;
    }
    __syncthreads();

    int excl = wsum[wid] + (v - sum);
    int run = excl;
    for (int i = start; i < end; i++) {
        off[i] = run;
        cur[i] = run;
        run += cnt[i];
    }
    if (t == 1023) off[n] = run;
}

__global__ void k_fill_all(const int* __restrict__ eidx, const int* __restrict__ vidx) {
    int i = blockIdx.x * blockDim.x + threadIdx.x;
    if (i < PX) {
        int pe = atomicAdd(&g_cur_e[eidx[i]], 1);
        g_perm_e[pe] = i;
        int pv = atomicAdd(&g_cur_v[vidx[i]], 1);
        g_perm_v[pv] = i;
    }
}

// ---------------- split-bf16 tensor-core GEMM ----------------
// C[m,n] = relu(sum_k A[m,k]*B[n,k] + bias[n]) * rowscale[m]
// A fp32 [M,256] row-major, B fp32 [256,256] row-major (row n k-contiguous).
// Each fp32 x split as x = hi + lo (bf16); C = Ah*Bh + Ah*Bl + Al*Bh via
// mma.sync.m16n8k16.bf16 with fp32 accumulators.
#define BM 128
#define BN 128
#define BK 32
#define SP 20   // smem row stride in b32 units (16 data + 4 pad -> conflict-free frags)

__device__ __forceinline__ unsigned pack_bf16(float x0, float x1) {
    __nv_bfloat16 h0 = __float2bfloat16(x0);
    __nv_bfloat16 h1 = __float2bfloat16(x1);
    return (unsigned)__bfloat16_as_ushort(h0) | ((unsigned)__bfloat16_as_ushort(h1) << 16);
}

__device__ __forceinline__ void mma_bf16(float* c, const unsigned* a, const unsigned* b) {
    asm volatile(
        "mma.sync.aligned.m16n8k16.row.col.f32.bf16.bf16.f32 "
        "{%0,%1,%2,%3}, {%4,%5,%6,%7}, {%8,%9}, {%0,%1,%2,%3};"
        : "+f"(c[0]), "+f"(c[1]), "+f"(c[2]), "+f"(c[3])
        : "r"(a[0]), "r"(a[1]), "r"(a[2]), "r"(a[3]), "r"(b[0]), "r"(b[1]));
}

template <bool VE>
__global__ void __launch_bounds__(256)
k_gemm_bf16(const float* __restrict__ A, const float* __restrict__ B,
            const float* __restrict__ bias, const float* __restrict__ rowscale, int M) {
    float* C = VE ? g_ve : g_ev;
    __shared__ unsigned As_hi[BM * SP], As_lo[BM * SP];
    __shared__ unsigned Bs_hi[BN * SP], Bs_lo[BN * SP];

    const int tid = threadIdx.x;
    const int bm = blockIdx.x * BM;
    const int bn = blockIdx.y * BN;
    const int wid = tid >> 5, lane = tid & 31;
    const int gid = lane >> 2, tid4 = lane & 3;
    const int wm = (wid & 1) * 64;    // warp M offset (2 warps in M)
    const int wn = (wid >> 1) * 32;   // warp N offset (4 warps in N)

    float acc[4][4][4];               // [mt][nt][c0..c3]
#pragma unroll
    for (int mt = 0; mt < 4; mt++)
#pragma unroll
        for (int nt = 0; nt < 4; nt++)
#pragma unroll
            for (int q = 0; q < 4; q++) acc[mt][nt][q] = 0.f;

    for (int k0 = 0; k0 < HD; k0 += BK) {
        // ---- stage: gmem fp32 -> smem split bf16 (hi/lo) ----
#pragma unroll
        for (int i = 0; i < 4; i++) {
            int f = tid + i * 256;          // 0..1023 float4 slots (128 rows x 8)
            int row = f >> 3;
            int c4 = f & 7;
            int gm = bm + row;
            float4 av = (gm < M) ? *(const float4*)&A[(size_t)gm * HD + k0 + c4 * 4]
                                 : make_float4(0.f, 0.f, 0.f, 0.f);
            float h0 = __bfloat162float(__float2bfloat16(av.x));
            float h1 = __bfloat162float(__float2bfloat16(av.y));
            float h2 = __bfloat162float(__float2bfloat16(av.z));
            float h3 = __bfloat162float(__float2bfloat16(av.w));
            As_hi[row * SP + c4 * 2 + 0] = pack_bf16(h0, h1);
            As_hi[row * SP + c4 * 2 + 1] = pack_bf16(h2, h3);
            As_lo[row * SP + c4 * 2 + 0] = pack_bf16(av.x - h0, av.y - h1);
            As_lo[row * SP + c4 * 2 + 1] = pack_bf16(av.z - h2, av.w - h3);

            float4 wv = *(const float4*)&B[(size_t)(bn + row) * HD + k0 + c4 * 4];
            float w0 = __bfloat162float(__float2bfloat16(wv.x));
            float w1 = __bfloat162float(__float2bfloat16(wv.y));
            float w2 = __bfloat162float(__float2bfloat16(wv.z));
            float w3 = __bfloat162float(__float2bfloat16(wv.w));
            Bs_hi[row * SP + c4 * 2 + 0] = pack_bf16(w0, w1);
            Bs_hi[row * SP + c4 * 2 + 1] = pack_bf16(w2, w3);
            Bs_lo[row * SP + c4 * 2 + 0] = pack_bf16(wv.x - w0, wv.y - w1);
            Bs_lo[row * SP + c4 * 2 + 1] = pack_bf16(wv.z - w2, wv.w - w3);
        }
        __syncthreads();

        // ---- compute: 2 k-steps of 16 ----
#pragma unroll
        for (int ks = 0; ks < 2; ks++) {
            unsigned ah[4][4], al[4][4], bh[4][2], bl[4][2];
#pragma unroll
            for (int mt = 0; mt < 4; mt++) {
                int r = wm + mt * 16 + gid;
                int c = ks * 8 + tid4;
                ah[mt][0] = As_hi[r * SP + c];
                ah[mt][1] = As_hi[(r + 8) * SP + c];
                ah[mt][2] = As_hi[r * SP + c + 4];
                ah[mt][3] = As_hi[(r + 8) * SP + c + 4];
                al[mt][0] = As_lo[r * SP + c];
                al[mt][1] = As_lo[(r + 8) * SP + c];
                al[mt][2] = As_lo[r * SP + c + 4];
                al[mt][3] = As_lo[(r + 8) * SP + c + 4];
            }
#pragma unroll
            for (int nt = 0; nt < 4; nt++) {
                int r = wn + nt * 8 + gid;
                int c = ks * 8 + tid4;
                bh[nt][0] = Bs_hi[r * SP + c];
                bh[nt][1] = Bs_hi[r * SP + c + 4];
                bl[nt][0] = Bs_lo[r * SP + c];
                bl[nt][1] = Bs_lo[r * SP + c + 4];
            }
#pragma unroll
            for (int mt = 0; mt < 4; mt++)
#pragma unroll
                for (int nt = 0; nt < 4; nt++) {
                    mma_bf16(acc[mt][nt], ah[mt], bh[nt]);
                    mma_bf16(acc[mt][nt], ah[mt], bl[nt]);
                    mma_bf16(acc[mt][nt], al[mt], bh[nt]);
                }
        }
        __syncthreads();
    }

    // ---- epilogue: bias + relu + rowscale ----
#pragma unroll
    for (int mt = 0; mt < 4; mt++) {
        int rm0 = bm + wm + mt * 16 + gid;
        int rm1 = rm0 + 8;
        float sc0 = (rm0 < M) ? rowscale[rm0] : 0.f;
        float sc1 = (rm1 < M) ? rowscale[rm1] : 0.f;
#pragma unroll
        for (int nt = 0; nt < 4; nt++) {
            int cn = bn + wn + nt * 8 + tid4 * 2;
            float b0f = bias[cn], b1f = bias[cn + 1];
            if (rm0 < M) {
                float2 o;
                o.x = fmaxf(acc[mt][nt][0] + b0f, 0.f) * sc0;
                o.y = fmaxf(acc[mt][nt][1] + b1f, 0.f) * sc0;
                *(float2*)&C[(size_t)rm0 * HD + cn] = o;
            }
            if (rm1 < M) {
                float2 o;
                o.x = fmaxf(acc[mt][nt][2] + b0f, 0.f) * sc1;
                o.y = fmaxf(acc[mt][nt][3] + b1f, 0.f) * sc1;
                *(float2*)&C[(size_t)rm1 * HD + cn] = o;
            }
        }
    }
}

// ---------------- pull-based accumulation ----------------
// e_out[j,h] = (e[j,h] + sum_{p: eidx[p]==j} g_ve[pairs_v[p],h] * n_reg_weight[p]) / e_reg_sum[j]
__global__ void k_edge_accum(const float* __restrict__ e, const int* __restrict__ pairs_v,
                             const float* __restrict__ nrw, const float* __restrict__ ers,
                             float* __restrict__ e_out) {
    __shared__ int srow[256];
    __shared__ float sw[256];
    int j = blockIdx.x;
    int h = threadIdx.x;
    int s = g_off_e[j], t = g_off_e[j + 1];
    float acc = e[(size_t)j * HD + h];
    for (int c = s; c < t; c += 256) {
        int i = c + h;
        if (i < t) {
            int p = g_perm_e[i];
            srow[h] = pairs_v[p];
            sw[h] = nrw[p];
        }
        __syncthreads();
        int m = min(256, t - c);
#pragma unroll 4
        for (int q = 0; q < m; q++)
            acc = fmaf(g_ve[(size_t)srow[q] * HD + h], sw[q], acc);
        __syncthreads();
    }
    e_out[(size_t)j * HD + h] = acc / ers[j];
}

// v_out[i,h] = (v[i,h]*n_weight[i] + sum_{p: vidx[p]==i} g_ev[pairs_e[p],h] * e_reg_weight[p]) / n_reg_sum[i]
__global__ void k_vertex_accum(const float* __restrict__ v, const int* __restrict__ pairs_e,
                               const float* __restrict__ erw, const float* __restrict__ nrs,
                               const float* __restrict__ nw, float* __restrict__ v_out) {
    __shared__ int srow[256];
    __shared__ float sw[256];
    int i0 = blockIdx.x;
    int h = threadIdx.x;
    int s = g_off_v[i0], t = g_off_v[i0 + 1];
    float acc = v[(size_t)i0 * HD + h] * nw[i0];
    for (int c = s; c < t; c += 256) {
        int i = c + h;
        if (i < t) {
            int p = g_perm_v[i];
            srow[h] = pairs_e[p];
            sw[h] = erw[p];
        }
        __syncthreads();
        int m = min(256, t - c);
#pragma unroll 4
        for (int q = 0; q < m; q++)
            acc = fmaf(g_ev[(size_t)srow[q] * HD + h], sw[q], acc);
        __syncthreads();
    }
    v_out[(size_t)i0 * HD + h] = acc / nrs[i0];
}

// ---------------- launcher: kernel launches ONLY ----------------
extern "C" void kernel_launch(void* const* d_in, const int* in_sizes, int n_in,
                              void* d_out, int out_size) {
    const float* v            = (const float*)d_in[0];
    const float* e            = (const float*)d_in[1];
    const float* W1           = (const float*)d_in[2];
    const float* b1           = (const float*)d_in[3];
    const float* W2           = (const float*)d_in[4];
    const float* b2           = (const float*)d_in[5];
    const float* n_weight     = (const float*)d_in[6];
    const float* e_weight     = (const float*)d_in[7];
    const float* n_reg_weight = (const float*)d_in[8];
    const float* e_reg_weight = (const float*)d_in[9];
    const float* e_reg_sum    = (const float*)d_in[10];
    const float* n_reg_sum    = (const float*)d_in[11];
    const int*   pairs_v      = (const int*)d_in[12];
    const int*   eidx         = (const int*)d_in[13];
    const int*   pairs_e      = (const int*)d_in[14];
    const int*   vidx         = (const int*)d_in[15];

    float* v_out = (float*)d_out;                              // [NVX, HD]
    float* e_out = (float*)d_out + (size_t)NVX * HD;           // [NEX, HD]

    // CSR build for both sides (4 launches)
    k_zero_all<<<(NVX + 255) / 256, 256>>>();
    k_hist_all<<<(PX + 255) / 256, 256>>>(eidx, vidx);
    k_scan_all<<<2, 1024>>>();
    k_fill_all<<<(PX + 255) / 256, 256>>>(eidx, vidx);

    // GEMM1: g_ve = relu(v @ W1^T + b1) * n_weight
    dim3 g1((NVX + BM - 1) / BM, HD / BN);
    k_gemm_bf16<true><<<g1, 256>>>(v, W1, b1, n_weight, NVX);

    // edge accumulate -> e_out (written straight into d_out)
    k_edge_accum<<<NEX, 256>>>(e, pairs_v, n_reg_weight, e_reg_sum, e_out);

    // GEMM2: g_ev = relu(e_out @ W2^T + b2) * e_weight
    dim3 g2((NEX + BM - 1) / BM, HD / BN);
    k_gemm_bf16<false><<<g2, 256>>>(e_out, W2, b2, e_weight, NEX);

    // vertex accumulate -> v_out
    k_vertex_accum<<<NVX, 256>>>(v, pairs_e, e_reg_weight, n_reg_sum, n_weight, v_out);
}